// round 16
// baseline (speedup 1.0000x reference)
#include <cuda_runtime.h>
#include <cuda_fp16.h>
#include <stdint.h>

#define SQ   2048
#define DM   1024
#define NH   16
#define DH   64
#define BT   4
#define ROWS (BT * SQ)   // 8192

// ---------------- scratch (device globals; no allocation allowed) ----------
__device__ __half g_qhi[(size_t)ROWS * DM];
__device__ __half g_qlo[(size_t)ROWS * DM];
__device__ __half g_kf [(size_t)ROWS * DM];
__device__ __half g_vf [(size_t)ROWS * DM];
__device__ __half g_xhi[(size_t)ROWS * DM];
__device__ __half g_xlo[(size_t)ROWS * DM];
__device__ __half g_ahi[(size_t)ROWS * DM];
__device__ __half g_alo[(size_t)ROWS * DM];
__device__ __half g_wt [(size_t)3 * DM * DM];   // [n_global][k]

// ---------------- PTX helpers (sm_103-safe: no tcgen05) --------------------
__device__ __forceinline__ uint32_t s2u(const void* p) {
    uint32_t a;
    asm("{ .reg .u64 t; cvta.to.shared.u64 t, %1; cvt.u32.u64 %0, t; }"
        : "=r"(a) : "l"(p));
    return a;
}
__device__ __forceinline__ void cpa16(uint32_t dst, const void* src) {
    asm volatile("cp.async.cg.shared.global [%0], [%1], 16;"
                 :: "r"(dst), "l"(src));
}
__device__ __forceinline__ void cpa_commit() {
    asm volatile("cp.async.commit_group;" ::: "memory");
}
template <int N>
__device__ __forceinline__ void cpa_wait() {
    asm volatile("cp.async.wait_group %0;" :: "n"(N) : "memory");
}
__device__ __forceinline__ void ldm4(uint32_t* r, uint32_t addr) {
    asm volatile("ldmatrix.sync.aligned.m8n8.x4.shared.b16 {%0,%1,%2,%3}, [%4];"
                 : "=r"(r[0]), "=r"(r[1]), "=r"(r[2]), "=r"(r[3]) : "r"(addr));
}
__device__ __forceinline__ void ldm4t(uint32_t* r, uint32_t addr) {
    asm volatile("ldmatrix.sync.aligned.m8n8.x4.trans.shared.b16 {%0,%1,%2,%3}, [%4];"
                 : "=r"(r[0]), "=r"(r[1]), "=r"(r[2]), "=r"(r[3]) : "r"(addr));
}
__device__ __forceinline__ void mma16816(float* c, const uint32_t* a,
                                         uint32_t b0, uint32_t b1) {
    asm volatile("mma.sync.aligned.m16n8k16.row.col.f32.f16.f16.f32 "
                 "{%0,%1,%2,%3}, {%4,%5,%6,%7}, {%8,%9}, {%0,%1,%2,%3};"
                 : "+f"(c[0]), "+f"(c[1]), "+f"(c[2]), "+f"(c[3])
                 : "r"(a[0]), "r"(a[1]), "r"(a[2]), "r"(a[3]),
                   "r"(b0), "r"(b1));
}
__device__ __forceinline__ uint32_t sw128(uint32_t off) {
    return off ^ ((off >> 3) & 0x70);
}
__device__ __forceinline__ uint32_t packh(float x, float y) {
    __half h0 = __float2half_rn(x), h1 = __float2half_rn(y);
    return ((uint32_t)__half_as_ushort(h1) << 16) | __half_as_ushort(h0);
}

// MUFU-free exp: exp(x) via 2^t, deg-5 poly on [-0.5,0.5], rel err ~3e-6.
__device__ __forceinline__ float fexp(float x) {
    x = fmaxf(x, -87.0f);
    float t = x * 1.4426950408889634f;
    float z = t + 12582912.0f;
    float n = z - 12582912.0f;
    float f = t - n;
    float p = 0.00133336f;
    p = fmaf(p, f, 0.00961813f);
    p = fmaf(p, f, 0.05550411f);
    p = fmaf(p, f, 0.24022651f);
    p = fmaf(p, f, 0.69314718f);
    p = fmaf(p, f, 1.0f);
    int sc = (__float_as_int(z) + (127 - 0x4B400000)) << 23;
    return __int_as_float(sc) * p;
}

// ---------------- conversion kernels ---------------------------------------
__global__ void cvt_split(const float* __restrict__ s,
                          __half* __restrict__ hi,
                          __half* __restrict__ lo) {
    int i = blockIdx.x * blockDim.x + threadIdx.x;
    float4 v = ((const float4*)s)[i];
    __half h0 = __float2half_rn(v.x), h1 = __float2half_rn(v.y);
    __half h2 = __float2half_rn(v.z), h3 = __float2half_rn(v.w);
    ((uint32_t*)hi)[2 * i]     = ((uint32_t)__half_as_ushort(h1) << 16) | __half_as_ushort(h0);
    ((uint32_t*)hi)[2 * i + 1] = ((uint32_t)__half_as_ushort(h3) << 16) | __half_as_ushort(h2);
    ((uint32_t*)lo)[2 * i]     = packh(v.x - __half2float(h0), v.y - __half2float(h1));
    ((uint32_t*)lo)[2 * i + 1] = packh(v.z - __half2float(h2), v.w - __half2float(h3));
}

__global__ void cvt_wqkv(const float* __restrict__ Qw,
                         const float* __restrict__ Kw,
                         const float* __restrict__ Vw) {
    int id = blockIdx.x * blockDim.x + threadIdx.x;
    int k = id & (DM - 1);
    int n = (id >> 10) & (DM - 1);
    int w = id >> 20;
    const float* W = (w == 0) ? Qw : (w == 1) ? Kw : Vw;
    float v = W[(size_t)(n >> 6) * (DM * DH) + (size_t)k * DH + (n & 63)];
    g_wt[id] = __float2half_rn(v);
}

__global__ void cvt_wo(const float* __restrict__ W) {
    int id = blockIdx.x * blockDim.x + threadIdx.x;
    int k = id & (DM - 1);
    int n = id >> 10;
    g_wt[id] = __float2half_rn(W[(size_t)k * DM + n]);
}

// ---------------- fused QKV GEMM (fp16 2-pass) ------------------------------
#define G_STAGE 49152              // Ahi 16K | Alo 16K | B 16K
#define G_SMEM  (2 * G_STAGE)

__global__ __launch_bounds__(256) void qkv_gemm(
    const __half* __restrict__ Ahi,
    const __half* __restrict__ Alo,
    const float* __restrict__ Qb,
    const float* __restrict__ Kb,
    const float* __restrict__ Vb)
{
    extern __shared__ char smem[];
    const uint32_t sb = s2u(smem);
    const int tid  = threadIdx.x;
    const int lane = tid & 31;
    const int wid  = tid >> 5;
    const int mw   = wid & 3;
    const int nw   = wid >> 2;
    const int n0 = blockIdx.x * 128;
    const int m0 = blockIdx.y * 128;

    auto load_chunk = [&](int c, int s) {
        const uint32_t ab = sb + s * G_STAGE;
        const int row = tid >> 1;
        const size_t arow = (size_t)(m0 + row) * DM;
        const size_t brow = (size_t)(n0 + row) * DM;
        const size_t kof = (size_t)c * 64;
#pragma unroll
        for (int i = 0; i < 4; i++) {
            const int seg = ((tid & 1) << 2) + i;
            const uint32_t sw = sw128(row * 128 + seg * 16);
            const size_t ka = kof + seg * 8;
            cpa16(ab + sw,         Ahi  + arow + ka);
            cpa16(ab + 16384 + sw, Alo  + arow + ka);
            cpa16(ab + 32768 + sw, g_wt + brow + ka);
        }
        cpa_commit();
    };

    float acc[2][8][4];
#pragma unroll
    for (int i = 0; i < 2; i++)
#pragma unroll
        for (int j = 0; j < 8; j++)
#pragma unroll
            for (int q = 0; q < 4; q++) acc[i][j][q] = 0.f;

    load_chunk(0, 0);
    load_chunk(1, 1);

    const int a_r = (lane & 15);
    const int a_k = (lane >> 4) * 8;
    const int b_n = (lane & 7) + ((lane >> 4) & 1) * 8;
    const int b_k = ((lane >> 3) & 1) * 8;

    for (int c = 0; c < 16; c++) {
        const int s = c & 1;
        if (c == 15) cpa_wait<0>(); else cpa_wait<1>();
        __syncthreads();
        const uint32_t ab = sb + s * G_STAGE;

#pragma unroll
        for (int ks = 0; ks < 4; ks++) {
            uint32_t ah[2][4], al[2][4], bh[4][4];
#pragma unroll
            for (int i = 0; i < 2; i++) {
                const int row = mw * 32 + i * 16 + a_r;
                const uint32_t sw = sw128(row * 128 + (ks * 16 + a_k) * 2);
                ldm4(ah[i], ab + sw);
                ldm4(al[i], ab + 16384 + sw);
            }
#pragma unroll
            for (int jp = 0; jp < 4; jp++) {
                const int nr = nw * 64 + jp * 16 + b_n;
                const uint32_t sw = sw128(nr * 128 + (ks * 16 + b_k) * 2);
                ldm4(bh[jp], ab + 32768 + sw);
            }
#pragma unroll
            for (int i = 0; i < 2; i++)
#pragma unroll
                for (int j = 0; j < 8; j++) {
                    const int jp = j >> 1, jo = (j & 1) * 2;
                    mma16816(acc[i][j], ah[i], bh[jp][jo], bh[jp][jo + 1]);
                    mma16816(acc[i][j], al[i], bh[jp][jo], bh[jp][jo + 1]);
                }
        }
        __syncthreads();
        if (c + 2 < 16) load_chunk(c + 2, s);
    }

    const int g  = lane >> 2;
    const int t2 = (lane & 3) * 2;
#pragma unroll
    for (int i = 0; i < 2; i++) {
#pragma unroll
        for (int half = 0; half < 2; half++) {
            const int row = m0 + mw * 32 + i * 16 + g + half * 8;
            const int bb = row >> 11, ss = row & 2047;
#pragma unroll
            for (int j = 0; j < 8; j++) {
                const int col = n0 + nw * 64 + j * 8 + t2;
                const int sel = col >> 10;
                const int c1  = col & 1023;
                const float* bias = (sel == 0) ? Qb : (sel == 1) ? Kb : Vb;
                float vx = acc[i][j][half * 2 + 0] + bias[c1 + 0];
                float vy = acc[i][j][half * 2 + 1] + bias[c1 + 1];
                const int hh = c1 >> 6;
                const int d  = c1 & 63;
                const size_t idx = (((size_t)(bb * NH + hh)) * SQ + ss) * DH + d;
                if (sel == 0) {
                    __half h0 = __float2half_rn(vx);
                    __half h1 = __float2half_rn(vy);
                    *(uint32_t*)&g_qhi[idx] =
                        ((uint32_t)__half_as_ushort(h1) << 16) | __half_as_ushort(h0);
                    *(uint32_t*)&g_qlo[idx] =
                        packh(vx - __half2float(h0), vy - __half2float(h1));
                } else if (sel == 1) {
                    *(uint32_t*)&g_kf[idx] = packh(vx, vy);
                } else {
                    *(uint32_t*)&g_vf[idx] = packh(vx, vy);
                }
            }
        }
    }
}

// ---------------- O-projection GEMM (fp16 2-pass) ---------------------------
__global__ __launch_bounds__(256) void o_gemm(
    const __half* __restrict__ Ahi,
    const __half* __restrict__ Alo,
    const float* __restrict__ bias,
    float* __restrict__ Cout)
{
    extern __shared__ char smem[];
    const uint32_t sb = s2u(smem);
    const int tid  = threadIdx.x;
    const int lane = tid & 31;
    const int wid  = tid >> 5;
    const int mw   = wid & 3;
    const int nw   = wid >> 2;
    const int n0 = blockIdx.x * 128;
    const int m0 = blockIdx.y * 128;

    auto load_chunk = [&](int c, int s) {
        const uint32_t ab = sb + s * G_STAGE;
        const int row = tid >> 1;
        const size_t arow = (size_t)(m0 + row) * DM;
        const size_t brow = (size_t)(n0 + row) * DM;
        const size_t kof = (size_t)c * 64;
#pragma unroll
        for (int i = 0; i < 4; i++) {
            const int seg = ((tid & 1) << 2) + i;
            const uint32_t sw = sw128(row * 128 + seg * 16);
            const size_t ka = kof + seg * 8;
            cpa16(ab + sw,         Ahi  + arow + ka);
            cpa16(ab + 16384 + sw, Alo  + arow + ka);
            cpa16(ab + 32768 + sw, g_wt + brow + ka);
        }
        cpa_commit();
    };

    float acc[2][8][4];
#pragma unroll
    for (int i = 0; i < 2; i++)
#pragma unroll
        for (int j = 0; j < 8; j++)
#pragma unroll
            for (int q = 0; q < 4; q++) acc[i][j][q] = 0.f;

    load_chunk(0, 0);
    load_chunk(1, 1);

    const int a_r = (lane & 15);
    const int a_k = (lane >> 4) * 8;
    const int b_n = (lane & 7) + ((lane >> 4) & 1) * 8;
    const int b_k = ((lane >> 3) & 1) * 8;

    for (int c = 0; c < 16; c++) {
        const int s = c & 1;
        if (c == 15) cpa_wait<0>(); else cpa_wait<1>();
        __syncthreads();
        const uint32_t ab = sb + s * G_STAGE;

#pragma unroll
        for (int ks = 0; ks < 4; ks++) {
            uint32_t ah[2][4], al[2][4], bh[4][4];
#pragma unroll
            for (int i = 0; i < 2; i++) {
                const int row = mw * 32 + i * 16 + a_r;
                const uint32_t sw = sw128(row * 128 + (ks * 16 + a_k) * 2);
                ldm4(ah[i], ab + sw);
                ldm4(al[i], ab + 16384 + sw);
            }
#pragma unroll
            for (int jp = 0; jp < 4; jp++) {
                const int nr = nw * 64 + jp * 16 + b_n;
                const uint32_t sw = sw128(nr * 128 + (ks * 16 + b_k) * 2);
                ldm4(bh[jp], ab + 32768 + sw);
            }
#pragma unroll
            for (int i = 0; i < 2; i++)
#pragma unroll
                for (int j = 0; j < 8; j++) {
                    const int jp = j >> 1, jo = (j & 1) * 2;
                    mma16816(acc[i][j], ah[i], bh[jp][jo], bh[jp][jo + 1]);
                    mma16816(acc[i][j], al[i], bh[jp][jo], bh[jp][jo + 1]);
                }
        }
        __syncthreads();
        if (c + 2 < 16) load_chunk(c + 2, s);
    }

    const int g  = lane >> 2;
    const int t2 = (lane & 3) * 2;
#pragma unroll
    for (int i = 0; i < 2; i++)
#pragma unroll
        for (int half = 0; half < 2; half++) {
            const int row = m0 + mw * 32 + i * 16 + g + half * 8;
#pragma unroll
            for (int j = 0; j < 8; j++) {
                const int col = n0 + nw * 64 + j * 8 + t2;
                float2 v;
                v.x = acc[i][j][half * 2 + 0] + bias[col + 0];
                v.y = acc[i][j][half * 2 + 1] + bias[col + 1];
                *(float2*)&Cout[(size_t)row * DM + col] = v;
            }
        }
}

// ---------------- flash attention (fp16 2-pass, causal, 8 warps) ------------
// 256 threads, q-tile 128 rows, warp tile 16x64, k-tiles of 64 double-buffered.
// smem: Qhi[0,16K) Qlo[16K,32K); stage s at 32K+s*16K: K 8K | V 8K.
// launch_bounds(256,2): force <=128 regs -> 2 CTA/SM = 16 warps/SM.
#define ATTN_SMEM (32768 + 2 * 16384)

__global__ __launch_bounds__(256, 2) void attn_kernel()
{
    extern __shared__ char smem[];
    const uint32_t sb = s2u(smem);
    const int qt   = (SQ / 128 - 1) - (int)blockIdx.x;   // heavy tiles first
    const int h    = blockIdx.y;
    const int b    = blockIdx.z;
    const int tid  = threadIdx.x;
    const int lane = tid & 31;
    const int warp = tid >> 5;            // 0..7, rows [warp*16, warp*16+16)
    const int g    = lane >> 2;
    const int t2   = (lane & 3) * 2;

    const size_t base = ((size_t)(b * NH + h)) * SQ * DH;

    const int a_r = lane & 15;
    const int a_k = (lane >> 4) * 8;
    const int b_n = (lane & 7) + ((lane >> 4) & 1) * 8;
    const int b_k = ((lane >> 3) & 1) * 8;
    const int v_m = lane >> 3, v_r = lane & 7;

    // load Q tile (hi/lo): 1024 16B-segments per buffer, 256 threads x 4 reps
#pragma unroll
    for (int rep = 0; rep < 4; rep++) {
        const int gi  = tid + rep * 256;
        const int row = gi >> 3;
        const int seg = gi & 7;
        const uint32_t sw = sw128(row * 128 + seg * 16);
        const size_t src = base + (size_t)(qt * 128 + row) * DH + seg * 8;
        cpa16(sb + sw,         g_qhi + src);
        cpa16(sb + 16384 + sw, g_qlo + src);
    }

    auto load_kv = [&](int kt, int s) {
        const uint32_t st = sb + 32768 + s * 16384;
        const int row = tid >> 2;
        const size_t soff = base + (size_t)(kt * 64 + row) * DH;
#pragma unroll
        for (int q = 0; q < 2; q++) {
            const int seg = (tid & 3) * 2 + q;
            const uint32_t sw = sw128(row * 128 + seg * 16);
            cpa16(st + sw,        g_kf + soff + seg * 8);
            cpa16(st + 8192 + sw, g_vf + soff + seg * 8);
        }
    };

    load_kv(0, 0);
    cpa_commit();          // group0 = Q + kv(0)
    load_kv(1, 1);
    cpa_commit();          // group1 = kv(1)

    float o[8][4];
    float mi[2], li[2];
#pragma unroll
    for (int j = 0; j < 8; j++)
#pragma unroll
        for (int q = 0; q < 4; q++) o[j][q] = 0.f;
    mi[0] = mi[1] = -1e30f;
    li[0] = li[1] = 0.f;

    const int ktmax = 2 * qt + 1;
    for (int kt = 0; kt <= ktmax; kt++) {
        const int s = kt & 1;
        const uint32_t st = sb + 32768 + s * 16384;
        if (kt == ktmax) cpa_wait<0>(); else cpa_wait<1>();
        __syncthreads();

        // ---- S = Q K^T (2-pass; B frags reloaded per-use to cap regs) ----
        float sf[8][4];
#pragma unroll
        for (int j = 0; j < 8; j++)
#pragma unroll
            for (int q = 0; q < 4; q++) sf[j][q] = 0.f;

#pragma unroll
        for (int ks = 0; ks < 4; ks++) {
            uint32_t ah[4], al[4];
            {
                const int row = warp * 16 + a_r;
                const uint32_t sw = sw128(row * 128 + (ks * 16 + a_k) * 2);
                ldm4(ah, sb + sw);
                ldm4(al, sb + 16384 + sw);
            }
#pragma unroll
            for (int jp = 0; jp < 4; jp++) {
                uint32_t bh[4];
                const int nr = jp * 16 + b_n;
                const uint32_t sw = sw128(nr * 128 + (ks * 16 + b_k) * 2);
                ldm4(bh, st + sw);
                mma16816(sf[2 * jp],     ah, bh[0], bh[1]);
                mma16816(sf[2 * jp],     al, bh[0], bh[1]);
                mma16816(sf[2 * jp + 1], ah, bh[2], bh[3]);
                mma16816(sf[2 * jp + 1], al, bh[2], bh[3]);
            }
        }

        // ---- online softmax (MUFU-free exp) ----
        const bool diag = (kt >= 2 * qt);
#pragma unroll
        for (int hf = 0; hf < 2; hf++) {
            const int grow = qt * 128 + warp * 16 + g + hf * 8;
            float mx = -1e30f;
#pragma unroll
            for (int j = 0; j < 8; j++)
#pragma unroll
                for (int q2 = 0; q2 < 2; q2++) {
                    float v = sf[j][hf * 2 + q2] * 0.125f;
                    if (diag && (kt * 64 + j * 8 + t2 + q2) > grow)
                        v = -100000.0f;
                    sf[j][hf * 2 + q2] = v;
                    mx = fmaxf(mx, v);
                }
            mx = fmaxf(mx, __shfl_xor_sync(0xffffffffu, mx, 1));
            mx = fmaxf(mx, __shfl_xor_sync(0xffffffffu, mx, 2));
            const float mn = fmaxf(mi[hf], mx);
            const float fs = fexp(mi[hf] - mn);
            mi[hf] = mn;
            float rs = 0.f;
#pragma unroll
            for (int j = 0; j < 8; j++)
#pragma unroll
                for (int q2 = 0; q2 < 2; q2++) {
                    const float p = fexp(sf[j][hf * 2 + q2] - mn);
                    sf[j][hf * 2 + q2] = p;
                    rs += p;
                }
            rs += __shfl_xor_sync(0xffffffffu, rs, 1);
            rs += __shfl_xor_sync(0xffffffffu, rs, 2);
            li[hf] = li[hf] * fs + rs;
#pragma unroll
            for (int j = 0; j < 8; j++) {
                o[j][hf * 2 + 0] *= fs;
                o[j][hf * 2 + 1] *= fs;
            }
        }

        // ---- O += P V (2-pass on P; V frags reloaded per-use) ----
#pragma unroll
        for (int ks = 0; ks < 4; ks++) {
            uint32_t ph[4], pl[4];
#pragma unroll
            for (int r = 0; r < 4; r++) {
                const int j  = ks * 2 + (r >> 1);
                const int q0 = (r & 1) * 2;
                const float x0 = sf[j][q0], x1 = sf[j][q0 + 1];
                const __half h0 = __float2half_rn(x0);
                const __half h1 = __float2half_rn(x1);
                ph[r] = ((uint32_t)__half_as_ushort(h1) << 16)
                      | __half_as_ushort(h0);
                pl[r] = packh(x0 - __half2float(h0), x1 - __half2float(h1));
            }
#pragma unroll
            for (int dp = 0; dp < 4; dp++) {
                uint32_t vh[4];
                const int srow = ks * 16 + (v_m & 1) * 8 + v_r;
                const int dcol = dp * 16 + (v_m >> 1) * 8;
                const uint32_t sw = sw128(srow * 128 + dcol * 2);
                ldm4t(vh, st + 8192 + sw);
                mma16816(o[2 * dp],     ph, vh[0], vh[1]);
                mma16816(o[2 * dp],     pl, vh[0], vh[1]);
                mma16816(o[2 * dp + 1], ph, vh[2], vh[3]);
                mma16816(o[2 * dp + 1], pl, vh[2], vh[3]);
            }
        }

        __syncthreads();
        if (kt + 2 <= ktmax) load_kv(kt + 2, s);
        cpa_commit();
    }

    // ---- epilogue: O/l -> fp16 hi/lo for the O-proj GEMM ----
#pragma unroll
    for (int hf = 0; hf < 2; hf++) {
        const float inv = 1.0f / li[hf];
        const size_t row = (size_t)b * SQ + qt * 128 + warp * 16 + g + hf * 8;
#pragma unroll
        for (int j = 0; j < 8; j++) {
            const float x0 = o[j][hf * 2 + 0] * inv;
            const float x1 = o[j][hf * 2 + 1] * inv;
            const size_t idx = row * DM + h * DH + j * 8 + t2;
            const __half h0 = __float2half_rn(x0);
            const __half h1 = __float2half_rn(x1);
            *(uint32_t*)&g_ahi[idx] =
                ((uint32_t)__half_as_ushort(h1) << 16) | __half_as_ushort(h0);
            *(uint32_t*)&g_alo[idx] =
                packh(x0 - __half2float(h0), x1 - __half2float(h1));
        }
    }
}

// ---------------------------------------------------------------------------
extern "C" void kernel_launch(void* const* d_in, const int* in_sizes, int n_in,
                              void* d_out, int out_size)
{
    const float* x  = (const float*)d_in[0];
    const float* Qw = (const float*)d_in[1];
    const float* Qb = (const float*)d_in[2];
    const float* Kw = (const float*)d_in[3];
    const float* Kb = (const float*)d_in[4];
    const float* Vw = (const float*)d_in[5];
    const float* Vb = (const float*)d_in[6];
    const float* Ow = (const float*)d_in[7];
    const float* Ob = (const float*)d_in[8];
    float* out = (float*)d_out;

    cudaFuncSetAttribute(qkv_gemm, cudaFuncAttributeMaxDynamicSharedMemorySize, G_SMEM);
    cudaFuncSetAttribute(o_gemm,   cudaFuncAttributeMaxDynamicSharedMemorySize, G_SMEM);
    cudaFuncSetAttribute(attn_kernel, cudaFuncAttributeMaxDynamicSharedMemorySize, ATTN_SMEM);

    __half *xhi, *xlo, *ahi, *alo;
    cudaGetSymbolAddress((void**)&xhi, g_xhi);
    cudaGetSymbolAddress((void**)&xlo, g_xlo);
    cudaGetSymbolAddress((void**)&ahi, g_ahi);
    cudaGetSymbolAddress((void**)&alo, g_alo);

    cvt_split<<<ROWS * DM / 1024, 256>>>(x, xhi, xlo);
    cvt_wqkv<<<3 * DM * DM / 256, 256>>>(Qw, Kw, Vw);

    qkv_gemm<<<dim3(3 * DM / 128, ROWS / 128), 256, G_SMEM>>>(xhi, xlo, Qb, Kb, Vb);

    attn_kernel<<<dim3(SQ / 128, NH, BT), 256, ATTN_SMEM>>>();

    cvt_wo<<<DM * DM / 256, 256>>>(Ow);
    o_gemm<<<dim3(DM / 128, ROWS / 128), 256, G_SMEM>>>(ahi, alo, Ob, out);
}